// round 15
// baseline (speedup 1.0000x reference)
#include <cuda_runtime.h>
#include <cuda_fp16.h>
#include <cstdint>

#define BATCH 16
#define NNODE 1024
#define DIM 256
#define HEADS 4
#define NBR 1023
#define TSTEPS 20

// ---------------- scratch (device globals; no allocation allowed) ----------------
__device__ __half g_h0h[BATCH * NNODE * DIM];
__device__ __half g_h1h[BATCH * NNODE * DIM];
__device__ __half g_whh[BATCH * NNODE * DIM];
__device__ uint32_t g_wpack[3 * 128 * 256];
__device__ float g_pos[BATCH * NNODE * 2];
__device__ float g_as[BATCH * HEADS * NNODE];
__device__ float g_ad[BATCH * HEADS * NNODE];
__device__ uint32_t g_asmaxu[2 * BATCH * HEADS];
__device__ uint32_t g_adjT[BATCH * 32 * NNODE];

// ======================= helpers =======================
__device__ __forceinline__ void mma_f16(float* c, uint32_t a0, uint32_t a1,
                                        uint32_t a2, uint32_t a3,
                                        uint32_t b0, uint32_t b1) {
    asm volatile(
        "mma.sync.aligned.m16n8k16.row.col.f32.f16.f16.f32 "
        "{%0,%1,%2,%3}, {%4,%5,%6,%7}, {%8,%9}, {%0,%1,%2,%3};"
        : "+f"(c[0]), "+f"(c[1]), "+f"(c[2]), "+f"(c[3])
        : "r"(a0), "r"(a1), "r"(a2), "r"(a3), "r"(b0), "r"(b1));
}
__device__ __forceinline__ float slctf(float a, float b, float c) {
    float d;
    asm("slct.f32.f32 %0, %1, %2, %3;" : "=f"(d) : "f"(a), "f"(b), "f"(c));
    return d;
}
__device__ __forceinline__ uint32_t pack2(float lo, float hi) {
    uint32_t d;
    asm("cvt.rn.f16x2.f32 %0, %1, %2;" : "=r"(d) : "f"(hi), "f"(lo));
    return d;
}
__device__ __forceinline__ uint32_t prmtb(uint32_t a, uint32_t b, uint32_t s) {
    uint32_t d;
    asm("prmt.b32 %0, %1, %2, %3;" : "=r"(d) : "r"(a), "r"(b), "r"(s));
    return d;
}
__device__ __forceinline__ uint32_t fenc(float f) {
    uint32_t b = __float_as_uint(f);
    return ((int)b < 0) ? ~b : (b | 0x80000000u);
}
__device__ __forceinline__ float fdec(uint32_t u) {
    return __uint_as_float((u & 0x80000000u) ? (u ^ 0x80000000u) : ~u);
}

// ---------------- weight prep (+output-tail zero) ----------------
__global__ __launch_bounds__(256) void wprep_kernel(
    const float* __restrict__ gat_w, const float* __restrict__ proj_w,
    float* __restrict__ out, long long tstart, long long ttotal)
{
    if (blockIdx.x < 384) {
        int wsel = blockIdx.x >> 7;
        int kp = blockIdx.x & 127;
        int n = threadIdx.x;
        const float* W = (wsel < 2) ? gat_w + (size_t)wsel * 65536 : proj_w;
        float lo = W[(size_t)(2 * kp) * 256 + n];
        float hi = W[(size_t)(2 * kp + 1) * 256 + n];
        g_wpack[(size_t)wsel * 32768 + kp * 256 + n] = pack2(lo, hi);
    } else {
        long long i = tstart + (long long)(blockIdx.x - 384) * 256 + threadIdx.x;
        while (i < ttotal) { out[i] = 0.f; i += 64LL * 256; }
    }
}

// ---------------- embed: 8 nodes per block, fp16 output ----------------
__global__ __launch_bounds__(256) void embed_kernel(
    const float* __restrict__ ego, const float* __restrict__ nbr,
    const float* __restrict__ node_w, const float* __restrict__ node_b,
    const float* __restrict__ node_g, const float* __restrict__ node_bb,
    const float* __restrict__ ego_w, const float* __restrict__ ego_b,
    const float* __restrict__ ego_g, const float* __restrict__ ego_bb)
{
    int t = threadIdx.x;
    int bn0 = blockIdx.x * 8;
    __shared__ float f[8][5];
    __shared__ float ws[8][8], wq[8][8];
    if (t < 40) {
        int nn = t / 5, k = t - nn * 5;
        int bn = bn0 + nn;
        int b = bn >> 10, n = bn & 1023;
        float v = (n == 0) ? ego[(b * TSTEPS + TSTEPS - 1) * 7 + k]
                           : nbr[((b * NBR + (n - 1)) * TSTEPS + TSTEPS - 1) * 11 + k];
        f[nn][k] = v;
        if (k < 2) g_pos[bn * 2 + k] = v;
    }
    __syncthreads();
    float wn[5];
#pragma unroll
    for (int k = 0; k < 5; k++) wn[k] = node_w[k * DIM + t];
    float nb = node_b[t];
    int lane = t & 31, w = t >> 5;
    float vv[8];
#pragma unroll
    for (int nn = 0; nn < 8; nn++) {
        int n = (bn0 + nn) & 1023;
        float v;
        if (n == 0) {
            v = ego_b[t];
#pragma unroll
            for (int k = 0; k < 5; k++) v = fmaf(f[nn][k], ego_w[k * DIM + t], v);
        } else {
            v = nb;
#pragma unroll
            for (int k = 0; k < 5; k++) v = fmaf(f[nn][k], wn[k], v);
        }
        v = fmaxf(v, 0.f);
        vv[nn] = v;
        float s = v, q = v * v;
#pragma unroll
        for (int o = 16; o; o >>= 1) {
            s += __shfl_down_sync(0xffffffffu, s, o);
            q += __shfl_down_sync(0xffffffffu, q, o);
        }
        if (lane == 0) { ws[nn][w] = s; wq[nn][w] = q; }
    }
    __syncthreads();
    float ng = node_g[t], nbb = node_bb[t];
#pragma unroll
    for (int nn = 0; nn < 8; nn++) {
        int bn = bn0 + nn;
        int n = bn & 1023;
        float sum = 0.f, sq = 0.f;
#pragma unroll
        for (int i = 0; i < 8; i++) { sum += ws[nn][i]; sq += wq[nn][i]; }
        float mean = sum * (1.f / 256.f);
        float var = fmaxf(sq * (1.f / 256.f) - mean * mean, 0.f);
        float inv = rsqrtf(var + 1e-5f);
        float gg = ng, bb2 = nbb;
        if (n == 0) { gg = ego_g[t]; bb2 = ego_bb[t]; }
        g_h0h[(size_t)bn * DIM + t] = __float2half_rn((vv[nn] - mean) * inv * gg + bb2);
    }
}

// ---------------- adjacency bitmask + asmax buffer init ----------------
__global__ __launch_bounds__(256) void adj_kernel()
{
    int b = blockIdx.z, jw = blockIdx.y;
    int lane = threadIdx.x & 31, w = threadIdx.x >> 5;
    if (blockIdx.x == 0 && jw == 0 && threadIdx.x < 8) {
        int l = threadIdx.x >> 2, h = threadIdx.x & 3;
        g_asmaxu[l * (BATCH * HEADS) + b * HEADS + h] = 0u;
    }
    int j = jw * 32 + lane;
    float2 pj = ((const float2*)g_pos)[b * NNODE + j];
    int i0 = blockIdx.x * 32 + w;
#pragma unroll
    for (int q = 0; q < 4; q++) {
        int i = i0 + q * 8;
        float2 pi = ((const float2*)g_pos)[b * NNODE + i];
        float dx = pj.x - pi.x, dy = pj.y - pi.y;
        bool a = (fmaf(dx, dx, dy * dy) < 2500.f) || (i == j);
        uint32_t word = __ballot_sync(0xffffffffu, a);
        if (lane == 0) g_adjT[(b * 32 + jw) * NNODE + i] = word;
    }
}

// ---------------- fp16 GEMM 128x128 tile, warp covers one head (SAD in-warp) ----
#define GA_STRIDE 20
#define GBW_STRIDE 136
template <bool BIAS, bool SAD>
__global__ __launch_bounds__(256, 2) void tgemm256(
    const uint32_t* __restrict__ A_pack, const uint32_t* __restrict__ W_pack,
    const float* __restrict__ bias, float* __restrict__ Cf, __half* __restrict__ Ch,
    const float* __restrict__ asrc, const float* __restrict__ adst,
    int sadLayer)
{
    __shared__ uint32_t As_p[128 * GA_STRIDE];
    __shared__ uint32_t Bs_p[16 * GBW_STRIDE];
    int tid = threadIdx.x, w = tid >> 5, lane = tid & 31;
    int g4 = lane >> 2, q4 = lane & 3;
    int m0 = blockIdx.x * 128, n0 = blockIdx.y * 128;
    int wm = w & 3, wn = w >> 2;
    int r0 = wm * 32, c0 = wn * 64;

    int arow = tid >> 2, af4 = tid & 3;
    int brow = tid >> 4, bf4 = tid & 15;
    const uint4* Ag = (const uint4*)(A_pack + (size_t)(m0 + arow) * 128 + af4 * 4);
    const uint32_t* WgBase = W_pack + (size_t)brow * 256 + n0 + bf4 * 4;

    float acc[2][8][4];
#pragma unroll
    for (int mt = 0; mt < 2; mt++)
#pragma unroll
        for (int nt = 0; nt < 8; nt++)
#pragma unroll
            for (int k = 0; k < 4; k++) acc[mt][nt][k] = 0.f;

    uint4 pa0 = Ag[0];
    uint4 pa1 = Ag[(size_t)64 * 32];
    uint4 pb0 = *(const uint4*)WgBase;
    uint4 pb1 = *(const uint4*)(WgBase + 64);

    for (int kc = 0; kc < 8; kc++) {
        __syncthreads();
        *(uint4*)&As_p[arow * GA_STRIDE + af4 * 4] = pa0;
        *(uint4*)&As_p[(arow + 64) * GA_STRIDE + af4 * 4] = pa1;
        *(uint4*)&Bs_p[brow * GBW_STRIDE + bf4 * 4] = pb0;
        *(uint4*)&Bs_p[brow * GBW_STRIDE + 64 + bf4 * 4] = pb1;
        __syncthreads();
        if (kc < 7) {
            const uint4* Agn = (const uint4*)((const uint32_t*)Ag + (kc + 1) * 16);
            const uint32_t* Wgn = WgBase + (size_t)(kc + 1) * 16 * 256;
            pa0 = Agn[0];
            pa1 = Agn[(size_t)64 * 32];
            pb0 = *(const uint4*)Wgn;
            pb1 = *(const uint4*)(Wgn + 64);
        }
#pragma unroll
        for (int kbb = 0; kbb < 2; kbb++) {
            const uint32_t* ap = As_p + (r0 + g4) * GA_STRIDE + kbb * 8 + q4;
            uint32_t a00 = ap[0];
            uint32_t a01 = ap[8 * GA_STRIDE];
            uint32_t a02 = ap[4];
            uint32_t a03 = ap[8 * GA_STRIDE + 4];
            uint32_t a10 = ap[16 * GA_STRIDE];
            uint32_t a11 = ap[24 * GA_STRIDE];
            uint32_t a12 = ap[16 * GA_STRIDE + 4];
            uint32_t a13 = ap[24 * GA_STRIDE + 4];
            const uint32_t* bp = Bs_p + (kbb * 8 + q4) * GBW_STRIDE + c0 + g4;
#pragma unroll
            for (int nt = 0; nt < 8; nt++) {
                uint32_t b0 = bp[nt * 8];
                uint32_t b1 = bp[nt * 8 + 4 * GBW_STRIDE];
                mma_f16(acc[0][nt], a00, a01, a02, a03, b0, b1);
                mma_f16(acc[1][nt], a10, a11, a12, a13, b0, b1);
            }
        }
    }
    // ---- C store ----
#pragma unroll
    for (int mt = 0; mt < 2; mt++) {
        int row = m0 + r0 + mt * 16 + g4;
#pragma unroll
        for (int nt = 0; nt < 8; nt++) {
            int cc = nt * 8 + q4 * 2;
            if (BIAS) {
                float bx = bias[n0 + c0 + cc], by = bias[n0 + c0 + cc + 1];
                float2 u0, u1;
                u0.x = acc[mt][nt][0] + bx; u0.y = acc[mt][nt][1] + by;
                u1.x = acc[mt][nt][2] + bx; u1.y = acc[mt][nt][3] + by;
                *(float2*)&Cf[(size_t)row * 256 + n0 + c0 + cc] = u0;
                *(float2*)&Cf[(size_t)(row + 8) * 256 + n0 + c0 + cc] = u1;
            } else {
                *(uint32_t*)&Ch[(size_t)row * 256 + n0 + c0 + cc] =
                    pack2(acc[mt][nt][0], acc[mt][nt][1]);
                *(uint32_t*)&Ch[(size_t)(row + 8) * 256 + n0 + c0 + cc] =
                    pack2(acc[mt][nt][2], acc[mt][nt][3]);
            }
        }
    }
    // ---- fused a_src / a_dst + asmax: each warp owns head hh, rows r0..r0+31 ----
    if (SAD) {
        int hh = blockIdx.y * 2 + wn;
        int b = m0 >> 10;
        int bh = b * HEADS + hh;
        float as_c[16], ad_c[16];
#pragma unroll
        for (int nt = 0; nt < 8; nt++) {
            int cc = nt * 8 + q4 * 2;
            as_c[nt * 2] = asrc[hh * 64 + cc];
            as_c[nt * 2 + 1] = asrc[hh * 64 + cc + 1];
            ad_c[nt * 2] = adst[hh * 64 + cc];
            ad_c[nt * 2 + 1] = adst[hh * 64 + cc + 1];
        }
        float mloc = -1e30f;
#pragma unroll
        for (int mt = 0; mt < 2; mt++) {
            float sAs = 0.f, sAd = 0.f, sBs = 0.f, sBd = 0.f;
#pragma unroll
            for (int nt = 0; nt < 8; nt++) {
                sAs += acc[mt][nt][0] * as_c[nt * 2] + acc[mt][nt][1] * as_c[nt * 2 + 1];
                sBs += acc[mt][nt][2] * as_c[nt * 2] + acc[mt][nt][3] * as_c[nt * 2 + 1];
                sAd += acc[mt][nt][0] * ad_c[nt * 2] + acc[mt][nt][1] * ad_c[nt * 2 + 1];
                sBd += acc[mt][nt][2] * ad_c[nt * 2] + acc[mt][nt][3] * ad_c[nt * 2 + 1];
            }
#pragma unroll
            for (int o = 1; o < 4; o <<= 1) {
                sAs += __shfl_xor_sync(0xffffffffu, sAs, o);
                sAd += __shfl_xor_sync(0xffffffffu, sAd, o);
                sBs += __shfl_xor_sync(0xffffffffu, sBs, o);
                sBd += __shfl_xor_sync(0xffffffffu, sBd, o);
            }
            int n = (m0 & 1023) + r0 + mt * 16 + g4;
            if (q4 == 0) {
                g_as[bh * NNODE + n] = sAs;
                g_ad[bh * NNODE + n] = sAd;
                g_as[bh * NNODE + n + 8] = sBs;
                g_ad[bh * NNODE + n + 8] = sBd;
            }
            mloc = fmaxf(mloc, fmaxf(sAs, sBs));
        }
#pragma unroll
        for (int o = 16; o; o >>= 1)
            mloc = fmaxf(mloc, __shfl_xor_sync(0xffffffffu, mloc, o));
        if (lane == 0)
            atomicMax(&g_asmaxu[sadLayer * (BATCH * HEADS) + bh], fenc(mloc));
    }
}

// ---------------- GAT attention: fp16 m16n8k16 MMA, fp16 wh input ----
#define VP_STRIDE 72
__global__ __launch_bounds__(256, 2) void gat_attn_mma(
    const __half* __restrict__ whh, const float* __restrict__ gbias,
    __half* __restrict__ hout, int layer)
{
    __shared__ uint32_t v_p[32 * VP_STRIDE];
    __shared__ float4 je[64];
    __shared__ uint32_t adj_sm[512];

    int tid = threadIdx.x, w = tid >> 5, lane = tid & 31;
    int g4 = lane >> 2, q4 = lane & 3;
    int it = blockIdx.x, hh = blockIdx.y, b = blockIdx.z;
    int i0 = it * 256, bh = b * HEADS + hh;
    int r0 = w * 32;

    float F1[4], F2[4], adreg[4];
    {
        float mx = fdec(g_asmaxu[layer * (BATCH * HEADS) + bh]);
#pragma unroll
        for (int t = 0; t < 4; t++) {
            float ad = g_ad[bh * NNODE + i0 + r0 + t * 8 + g4];
            adreg[t] = ad;
            float mm = mx + ad;
            float mr = fmaxf(mm, 0.2f * mm);
            F1[t] = __expf(ad - mr);
            F2[t] = __expf(0.2f * ad - mr);
        }
    }
    {
        int jp = tid >> 3, cc = 64 + (tid & 7);
        v_p[jp * VP_STRIDE + cc] = (cc == 64) ? 0x3C003C00u : 0u;
    }

    float acc[2][9][4];
#pragma unroll
    for (int mt = 0; mt < 2; mt++)
#pragma unroll
        for (int n = 0; n < 9; n++)
#pragma unroll
            for (int k = 0; k < 4; k++) acc[mt][n][k] = 0.f;

    const __half* whb = whh + ((size_t)(b * NNODE)) * DIM + hh * 64;
    const uint32_t* adjb = g_adjT + (size_t)b * 32 * NNODE + i0;

    for (int ch = 0; ch < 16; ch++) {
        int j0c = ch * 64;
        __syncthreads();
        {
            int jp = tid >> 3, cb = (tid & 7) * 8;
            const uint4* rA = (const uint4*)(whb + (size_t)(j0c + 2 * jp) * DIM + cb);
            const uint4* rB = (const uint4*)(whb + (size_t)(j0c + 2 * jp + 1) * DIM + cb);
            uint4 a = rA[0], bb4 = rB[0];
            uint4 o0, o1;
            o0.x = prmtb(a.x, bb4.x, 0x5410); o0.y = prmtb(a.x, bb4.x, 0x7632);
            o0.z = prmtb(a.y, bb4.y, 0x5410); o0.w = prmtb(a.y, bb4.y, 0x7632);
            o1.x = prmtb(a.z, bb4.z, 0x5410); o1.y = prmtb(a.z, bb4.z, 0x7632);
            o1.z = prmtb(a.w, bb4.w, 0x5410); o1.w = prmtb(a.w, bb4.w, 0x7632);
            *(uint4*)&v_p[jp * VP_STRIDE + cb] = o0;
            *(uint4*)&v_p[jp * VP_STRIDE + cb + 4] = o1;
        }
        if (tid < 64) {
            float a = g_as[bh * NNODE + j0c + tid];
            je[tid] = make_float4(a, __expf(a), __expf(0.2f * a), 0.f);
        }
        adj_sm[tid] = adjb[(size_t)(2 * ch) * NNODE + tid];
        adj_sm[256 + tid] = adjb[(size_t)(2 * ch + 1) * NNODE + tid];
        __syncthreads();
        uint32_t Aw[2][4];
#pragma unroll
        for (int t = 0; t < 4; t++) {
            Aw[0][t] = adj_sm[r0 + t * 8 + g4];
            Aw[1][t] = adj_sm[256 + r0 + t * 8 + g4];
        }
        uint32_t andall = Aw[0][0] & Aw[0][1] & Aw[0][2] & Aw[0][3]
                        & Aw[1][0] & Aw[1][1] & Aw[1][2] & Aw[1][3];
        bool allones = __all_sync(0xffffffffu, andall == 0xffffffffu);

#pragma unroll
        for (int kb = 0; kb < 4; kb++) {
            int jlo = kb * 16 + 2 * q4;
            float4 jeA = je[jlo];
            float4 jeB = je[jlo + 1];
            float4 jeC = je[jlo + 8];
            float4 jeD = je[jlo + 9];
            uint32_t afr[2][4];
            if (allones) {
#pragma unroll
                for (int t = 0; t < 4; t++) {
                    float pa = slctf(jeA.y * F1[t], jeA.z * F2[t], jeA.x + adreg[t]);
                    float pb = slctf(jeB.y * F1[t], jeB.z * F2[t], jeB.x + adreg[t]);
                    float pc = slctf(jeC.y * F1[t], jeC.z * F2[t], jeC.x + adreg[t]);
                    float pd = slctf(jeD.y * F1[t], jeD.z * F2[t], jeD.x + adreg[t]);
                    afr[t >> 1][t & 1] = pack2(pa, pb);
                    afr[t >> 1][2 + (t & 1)] = pack2(pc, pd);
                }
            } else {
                int half = kb >> 1;
                int s = jlo & 31;
#pragma unroll
                for (int t = 0; t < 4; t++) {
                    uint32_t wv = Aw[half][t];
                    uint32_t b2lo = (wv >> s) & 3u;
                    uint32_t b2hi = (wv >> (s + 8)) & 3u;
                    uint32_t mlo = ((b2lo & 1u) ? 0x0000FFFFu : 0u) |
                                   ((b2lo & 2u) ? 0xFFFF0000u : 0u);
                    uint32_t mhi = ((b2hi & 1u) ? 0x0000FFFFu : 0u) |
                                   ((b2hi & 2u) ? 0xFFFF0000u : 0u);
                    float pa = slctf(jeA.y * F1[t], jeA.z * F2[t], jeA.x + adreg[t]);
                    float pb = slctf(jeB.y * F1[t], jeB.z * F2[t], jeB.x + adreg[t]);
                    float pc = slctf(jeC.y * F1[t], jeC.z * F2[t], jeC.x + adreg[t]);
                    float pd = slctf(jeD.y * F1[t], jeD.z * F2[t], jeD.x + adreg[t]);
                    afr[t >> 1][t & 1] = pack2(pa, pb) & mlo;
                    afr[t >> 1][2 + (t & 1)] = pack2(pc, pd) & mhi;
                }
            }
            const uint32_t* bp = v_p + (kb * 8 + q4) * VP_STRIDE + g4;
#pragma unroll
            for (int nt = 0; nt < 9; nt++) {
                uint32_t b0 = bp[nt * 8];
                uint32_t b1 = bp[nt * 8 + 4 * VP_STRIDE];
                mma_f16(acc[0][nt], afr[0][0], afr[0][1], afr[0][2], afr[0][3], b0, b1);
                mma_f16(acc[1][nt], afr[1][0], afr[1][1], afr[1][2], afr[1][3], b0, b1);
            }
        }
    }
    const float* bp = gbias + hh * 64;
#pragma unroll
    for (int mt = 0; mt < 2; mt++) {
        float z0 = __shfl_sync(0xffffffffu, acc[mt][8][0], lane & 28);
        float z1 = __shfl_sync(0xffffffffu, acc[mt][8][2], lane & 28);
        float iz0 = 1.f / z0;
        float iz1 = 1.f / z1;
        int rowg = i0 + r0 + mt * 16 + g4;
        __half* o0 = hout + ((size_t)(b * NNODE) + rowg) * DIM + hh * 64;
        __half* o1 = o0 + 8 * DIM;
#pragma unroll
        for (int nt = 0; nt < 8; nt++) {
            int cc = nt * 8 + q4 * 2;
            float bx = bp[cc], by = bp[cc + 1];
            float u0x = fmaxf(fmaf(acc[mt][nt][0], iz0, bx), 0.f);
            float u0y = fmaxf(fmaf(acc[mt][nt][1], iz0, by), 0.f);
            float u1x = fmaxf(fmaf(acc[mt][nt][2], iz1, bx), 0.f);
            float u1y = fmaxf(fmaf(acc[mt][nt][3], iz1, by), 0.f);
            *(uint32_t*)(o0 + cc) = pack2(u0x, u0y);
            *(uint32_t*)(o1 + cc) = pack2(u1x, u1y);
        }
    }
}

// ---------------- launch ----------------
extern "C" void kernel_launch(void* const* d_in, const int* in_sizes, int n_in,
                              void* d_out, int out_size)
{
    const float* ego      = (const float*)d_in[0];
    const float* nbr      = (const float*)d_in[1];
    const float* node_w   = (const float*)d_in[2];
    const float* node_b   = (const float*)d_in[3];
    const float* node_g   = (const float*)d_in[4];
    const float* node_bb  = (const float*)d_in[5];
    const float* ego_w    = (const float*)d_in[6];
    const float* ego_b    = (const float*)d_in[7];
    const float* ego_g    = (const float*)d_in[8];
    const float* ego_bb   = (const float*)d_in[9];
    const float* gat_w    = (const float*)d_in[10];
    const float* gat_asrc = (const float*)d_in[11];
    const float* gat_adst = (const float*)d_in[12];
    const float* gat_b    = (const float*)d_in[13];
    const float* proj_w   = (const float*)d_in[14];
    const float* proj_b   = (const float*)d_in[15];
    float* out = (float*)d_out;

    __half *h0h, *h1h, *whh;
    uint32_t* wpack;
    cudaGetSymbolAddress((void**)&h0h, g_h0h);
    cudaGetSymbolAddress((void**)&h1h, g_h1h);
    cudaGetSymbolAddress((void**)&whh, g_whh);
    cudaGetSymbolAddress((void**)&wpack, g_wpack);

    long long hsz = (long long)BATCH * NNODE * DIM;

    embed_kernel<<<BATCH * NNODE / 8, 256>>>(ego, nbr, node_w, node_b, node_g, node_bb,
                                             ego_w, ego_b, ego_g, ego_bb);
    adj_kernel<<<dim3(NNODE / 32, 32, BATCH), 256>>>();
    wprep_kernel<<<448, 256>>>(gat_w, proj_w, out, hsz, (long long)out_size);

    dim3 ggrid(BATCH * NNODE / 128, 2);
    __half* hbuf[2] = { h0h, h1h };
    for (int l = 0; l < 2; l++) {
        tgemm256<false, true><<<ggrid, 256>>>(
            (const uint32_t*)hbuf[l], wpack + (size_t)l * 32768,
            nullptr, nullptr, whh,
            gat_asrc + l * HEADS * 64, gat_adst + l * HEADS * 64, l);
        gat_attn_mma<<<dim3(4, HEADS, BATCH), 256>>>(whh, gat_b + l * DIM,
                                                     hbuf[1 - l], l);
    }
    tgemm256<true, false><<<ggrid, 256>>>(
        (const uint32_t*)h0h, wpack + 2 * 32768,
        proj_b, out, nullptr, nullptr, nullptr, 0);
}

// round 16
// speedup vs baseline: 1.0032x; 1.0032x over previous
#include <cuda_runtime.h>
#include <cuda_fp16.h>
#include <cstdint>

#define BATCH 16
#define NNODE 1024
#define DIM 256
#define HEADS 4
#define NBR 1023
#define TSTEPS 20

// ---------------- scratch (device globals; no allocation allowed) ----------------
__device__ __half g_h0h[BATCH * NNODE * DIM];
__device__ __half g_h1h[BATCH * NNODE * DIM];
__device__ __half g_whh[BATCH * NNODE * DIM];
__device__ uint32_t g_wpack[3 * 128 * 256];
__device__ float g_pos[BATCH * NNODE * 2];
__device__ float g_as[BATCH * HEADS * NNODE];
__device__ float g_ad[BATCH * HEADS * NNODE];
__device__ uint32_t g_asmaxu[2 * BATCH * HEADS];
__device__ uint32_t g_adjT[BATCH * 32 * NNODE];

// ======================= helpers =======================
__device__ __forceinline__ void mma_f16(float* c, uint32_t a0, uint32_t a1,
                                        uint32_t a2, uint32_t a3,
                                        uint32_t b0, uint32_t b1) {
    asm volatile(
        "mma.sync.aligned.m16n8k16.row.col.f32.f16.f16.f32 "
        "{%0,%1,%2,%3}, {%4,%5,%6,%7}, {%8,%9}, {%0,%1,%2,%3};"
        : "+f"(c[0]), "+f"(c[1]), "+f"(c[2]), "+f"(c[3])
        : "r"(a0), "r"(a1), "r"(a2), "r"(a3), "r"(b0), "r"(b1));
}
__device__ __forceinline__ float slctf(float a, float b, float c) {
    float d;
    asm("slct.f32.f32 %0, %1, %2, %3;" : "=f"(d) : "f"(a), "f"(b), "f"(c));
    return d;
}
__device__ __forceinline__ uint32_t pack2(float lo, float hi) {
    uint32_t d;
    asm("cvt.rn.f16x2.f32 %0, %1, %2;" : "=r"(d) : "f"(hi), "f"(lo));
    return d;
}
__device__ __forceinline__ uint32_t prmtb(uint32_t a, uint32_t b, uint32_t s) {
    uint32_t d;
    asm("prmt.b32 %0, %1, %2, %3;" : "=r"(d) : "r"(a), "r"(b), "r"(s));
    return d;
}
__device__ __forceinline__ uint32_t fenc(float f) {
    uint32_t b = __float_as_uint(f);
    return ((int)b < 0) ? ~b : (b | 0x80000000u);
}
__device__ __forceinline__ float fdec(uint32_t u) {
    return __uint_as_float((u & 0x80000000u) ? (u ^ 0x80000000u) : ~u);
}

// ---------------- weight prep (+output-tail zero) ----------------
__global__ __launch_bounds__(256) void wprep_kernel(
    const float* __restrict__ gat_w, const float* __restrict__ proj_w,
    float* __restrict__ out, long long tstart, long long ttotal)
{
    if (blockIdx.x < 384) {
        int wsel = blockIdx.x >> 7;
        int kp = blockIdx.x & 127;
        int n = threadIdx.x;
        const float* W = (wsel < 2) ? gat_w + (size_t)wsel * 65536 : proj_w;
        float lo = W[(size_t)(2 * kp) * 256 + n];
        float hi = W[(size_t)(2 * kp + 1) * 256 + n];
        g_wpack[(size_t)wsel * 32768 + kp * 256 + n] = pack2(lo, hi);
    } else {
        long long i = tstart + (long long)(blockIdx.x - 384) * 256 + threadIdx.x;
        while (i < ttotal) { out[i] = 0.f; i += 64LL * 256; }
    }
}

// ---------------- embed: 8 nodes per block, fp16 output ----------------
__global__ __launch_bounds__(256) void embed_kernel(
    const float* __restrict__ ego, const float* __restrict__ nbr,
    const float* __restrict__ node_w, const float* __restrict__ node_b,
    const float* __restrict__ node_g, const float* __restrict__ node_bb,
    const float* __restrict__ ego_w, const float* __restrict__ ego_b,
    const float* __restrict__ ego_g, const float* __restrict__ ego_bb)
{
    int t = threadIdx.x;
    int bn0 = blockIdx.x * 8;
    __shared__ float f[8][5];
    __shared__ float ws[8][8], wq[8][8];
    if (t < 40) {
        int nn = t / 5, k = t - nn * 5;
        int bn = bn0 + nn;
        int b = bn >> 10, n = bn & 1023;
        float v = (n == 0) ? ego[(b * TSTEPS + TSTEPS - 1) * 7 + k]
                           : nbr[((b * NBR + (n - 1)) * TSTEPS + TSTEPS - 1) * 11 + k];
        f[nn][k] = v;
        if (k < 2) g_pos[bn * 2 + k] = v;
    }
    __syncthreads();
    float wn[5];
#pragma unroll
    for (int k = 0; k < 5; k++) wn[k] = node_w[k * DIM + t];
    float nb = node_b[t];
    int lane = t & 31, w = t >> 5;
    float vv[8];
#pragma unroll
    for (int nn = 0; nn < 8; nn++) {
        int n = (bn0 + nn) & 1023;
        float v;
        if (n == 0) {
            v = ego_b[t];
#pragma unroll
            for (int k = 0; k < 5; k++) v = fmaf(f[nn][k], ego_w[k * DIM + t], v);
        } else {
            v = nb;
#pragma unroll
            for (int k = 0; k < 5; k++) v = fmaf(f[nn][k], wn[k], v);
        }
        v = fmaxf(v, 0.f);
        vv[nn] = v;
        float s = v, q = v * v;
#pragma unroll
        for (int o = 16; o; o >>= 1) {
            s += __shfl_down_sync(0xffffffffu, s, o);
            q += __shfl_down_sync(0xffffffffu, q, o);
        }
        if (lane == 0) { ws[nn][w] = s; wq[nn][w] = q; }
    }
    __syncthreads();
    float ng = node_g[t], nbb = node_bb[t];
#pragma unroll
    for (int nn = 0; nn < 8; nn++) {
        int bn = bn0 + nn;
        int n = bn & 1023;
        float sum = 0.f, sq = 0.f;
#pragma unroll
        for (int i = 0; i < 8; i++) { sum += ws[nn][i]; sq += wq[nn][i]; }
        float mean = sum * (1.f / 256.f);
        float var = fmaxf(sq * (1.f / 256.f) - mean * mean, 0.f);
        float inv = rsqrtf(var + 1e-5f);
        float gg = ng, bb2 = nbb;
        if (n == 0) { gg = ego_g[t]; bb2 = ego_bb[t]; }
        g_h0h[(size_t)bn * DIM + t] = __float2half_rn((vv[nn] - mean) * inv * gg + bb2);
    }
}

// ---------------- adjacency bitmask + asmax buffer init ----------------
__global__ __launch_bounds__(256) void adj_kernel()
{
    int b = blockIdx.z, jw = blockIdx.y;
    int lane = threadIdx.x & 31, w = threadIdx.x >> 5;
    if (blockIdx.x == 0 && jw == 0 && threadIdx.x < 8) {
        int l = threadIdx.x >> 2, h = threadIdx.x & 3;
        g_asmaxu[l * (BATCH * HEADS) + b * HEADS + h] = 0u;
    }
    int j = jw * 32 + lane;
    float2 pj = ((const float2*)g_pos)[b * NNODE + j];
    int i0 = blockIdx.x * 32 + w;
#pragma unroll
    for (int q = 0; q < 4; q++) {
        int i = i0 + q * 8;
        float2 pi = ((const float2*)g_pos)[b * NNODE + i];
        float dx = pj.x - pi.x, dy = pj.y - pi.y;
        bool a = (fmaf(dx, dx, dy * dy) < 2500.f) || (i == j);
        uint32_t word = __ballot_sync(0xffffffffu, a);
        if (lane == 0) g_adjT[(b * 32 + jw) * NNODE + i] = word;
    }
}

// ---------------- fp16 GEMM 128x128 tile, warp covers one head (SAD in-warp) ----
#define GA_STRIDE 20
#define GBW_STRIDE 136
template <bool BIAS, bool SAD>
__global__ __launch_bounds__(256, 2) void tgemm256(
    const uint32_t* __restrict__ A_pack, const uint32_t* __restrict__ W_pack,
    const float* __restrict__ bias, float* __restrict__ Cf, __half* __restrict__ Ch,
    const float* __restrict__ asrc, const float* __restrict__ adst,
    int sadLayer)
{
    __shared__ uint32_t As_p[128 * GA_STRIDE];
    __shared__ uint32_t Bs_p[16 * GBW_STRIDE];
    int tid = threadIdx.x, w = tid >> 5, lane = tid & 31;
    int g4 = lane >> 2, q4 = lane & 3;
    int m0 = blockIdx.x * 128, n0 = blockIdx.y * 128;
    int wm = w & 3, wn = w >> 2;
    int r0 = wm * 32, c0 = wn * 64;

    int arow = tid >> 2, af4 = tid & 3;
    int brow = tid >> 4, bf4 = tid & 15;
    const uint4* Ag = (const uint4*)(A_pack + (size_t)(m0 + arow) * 128 + af4 * 4);
    const uint32_t* WgBase = W_pack + (size_t)brow * 256 + n0 + bf4 * 4;

    float acc[2][8][4];
#pragma unroll
    for (int mt = 0; mt < 2; mt++)
#pragma unroll
        for (int nt = 0; nt < 8; nt++)
#pragma unroll
            for (int k = 0; k < 4; k++) acc[mt][nt][k] = 0.f;

    uint4 pa0 = Ag[0];
    uint4 pa1 = Ag[(size_t)64 * 32];
    uint4 pb0 = *(const uint4*)WgBase;
    uint4 pb1 = *(const uint4*)(WgBase + 64);

    for (int kc = 0; kc < 8; kc++) {
        __syncthreads();
        *(uint4*)&As_p[arow * GA_STRIDE + af4 * 4] = pa0;
        *(uint4*)&As_p[(arow + 64) * GA_STRIDE + af4 * 4] = pa1;
        *(uint4*)&Bs_p[brow * GBW_STRIDE + bf4 * 4] = pb0;
        *(uint4*)&Bs_p[brow * GBW_STRIDE + 64 + bf4 * 4] = pb1;
        __syncthreads();
        if (kc < 7) {
            const uint4* Agn = (const uint4*)((const uint32_t*)Ag + (kc + 1) * 16);
            const uint32_t* Wgn = WgBase + (size_t)(kc + 1) * 16 * 256;
            pa0 = Agn[0];
            pa1 = Agn[(size_t)64 * 32];
            pb0 = *(const uint4*)Wgn;
            pb1 = *(const uint4*)(Wgn + 64);
        }
#pragma unroll
        for (int kbb = 0; kbb < 2; kbb++) {
            const uint32_t* ap = As_p + (r0 + g4) * GA_STRIDE + kbb * 8 + q4;
            uint32_t a00 = ap[0];
            uint32_t a01 = ap[8 * GA_STRIDE];
            uint32_t a02 = ap[4];
            uint32_t a03 = ap[8 * GA_STRIDE + 4];
            uint32_t a10 = ap[16 * GA_STRIDE];
            uint32_t a11 = ap[24 * GA_STRIDE];
            uint32_t a12 = ap[16 * GA_STRIDE + 4];
            uint32_t a13 = ap[24 * GA_STRIDE + 4];
            const uint32_t* bp = Bs_p + (kbb * 8 + q4) * GBW_STRIDE + c0 + g4;
#pragma unroll
            for (int nt = 0; nt < 8; nt++) {
                uint32_t b0 = bp[nt * 8];
                uint32_t b1 = bp[nt * 8 + 4 * GBW_STRIDE];
                mma_f16(acc[0][nt], a00, a01, a02, a03, b0, b1);
                mma_f16(acc[1][nt], a10, a11, a12, a13, b0, b1);
            }
        }
    }
    // ---- C store ----
#pragma unroll
    for (int mt = 0; mt < 2; mt++) {
        int row = m0 + r0 + mt * 16 + g4;
#pragma unroll
        for (int nt = 0; nt < 8; nt++) {
            int cc = nt * 8 + q4 * 2;
            if (BIAS) {
                float bx = bias[n0 + c0 + cc], by = bias[n0 + c0 + cc + 1];
                float2 u0, u1;
                u0.x = acc[mt][nt][0] + bx; u0.y = acc[mt][nt][1] + by;
                u1.x = acc[mt][nt][2] + bx; u1.y = acc[mt][nt][3] + by;
                *(float2*)&Cf[(size_t)row * 256 + n0 + c0 + cc] = u0;
                *(float2*)&Cf[(size_t)(row + 8) * 256 + n0 + c0 + cc] = u1;
            } else {
                *(uint32_t*)&Ch[(size_t)row * 256 + n0 + c0 + cc] =
                    pack2(acc[mt][nt][0], acc[mt][nt][1]);
                *(uint32_t*)&Ch[(size_t)(row + 8) * 256 + n0 + c0 + cc] =
                    pack2(acc[mt][nt][2], acc[mt][nt][3]);
            }
        }
    }
    // ---- fused a_src / a_dst + asmax: each warp owns head hh, rows r0..r0+31 ----
    if (SAD) {
        int hh = blockIdx.y * 2 + wn;
        int b = m0 >> 10;
        int bh = b * HEADS + hh;
        float as_c[16], ad_c[16];
#pragma unroll
        for (int nt = 0; nt < 8; nt++) {
            int cc = nt * 8 + q4 * 2;
            as_c[nt * 2] = asrc[hh * 64 + cc];
            as_c[nt * 2 + 1] = asrc[hh * 64 + cc + 1];
            ad_c[nt * 2] = adst[hh * 64 + cc];
            ad_c[nt * 2 + 1] = adst[hh * 64 + cc + 1];
        }
        float mloc = -1e30f;
#pragma unroll
        for (int mt = 0; mt < 2; mt++) {
            float sAs = 0.f, sAd = 0.f, sBs = 0.f, sBd = 0.f;
#pragma unroll
            for (int nt = 0; nt < 8; nt++) {
                sAs += acc[mt][nt][0] * as_c[nt * 2] + acc[mt][nt][1] * as_c[nt * 2 + 1];
                sBs += acc[mt][nt][2] * as_c[nt * 2] + acc[mt][nt][3] * as_c[nt * 2 + 1];
                sAd += acc[mt][nt][0] * ad_c[nt * 2] + acc[mt][nt][1] * ad_c[nt * 2 + 1];
                sBd += acc[mt][nt][2] * ad_c[nt * 2] + acc[mt][nt][3] * ad_c[nt * 2 + 1];
            }
#pragma unroll
            for (int o = 1; o < 4; o <<= 1) {
                sAs += __shfl_xor_sync(0xffffffffu, sAs, o);
                sAd += __shfl_xor_sync(0xffffffffu, sAd, o);
                sBs += __shfl_xor_sync(0xffffffffu, sBs, o);
                sBd += __shfl_xor_sync(0xffffffffu, sBd, o);
            }
            int n = (m0 & 1023) + r0 + mt * 16 + g4;
            if (q4 == 0) {
                g_as[bh * NNODE + n] = sAs;
                g_ad[bh * NNODE + n] = sAd;
                g_as[bh * NNODE + n + 8] = sBs;
                g_ad[bh * NNODE + n + 8] = sBd;
            }
            mloc = fmaxf(mloc, fmaxf(sAs, sBs));
        }
#pragma unroll
        for (int o = 16; o; o >>= 1)
            mloc = fmaxf(mloc, __shfl_xor_sync(0xffffffffu, mloc, o));
        if (lane == 0)
            atomicMax(&g_asmaxu[sadLayer * (BATCH * HEADS) + bh], fenc(mloc));
    }
}

// ---------------- GAT attention: fp16 m16n8k16 MMA, fp16 wh input ----
#define VP_STRIDE 72
__global__ __launch_bounds__(256, 2) void gat_attn_mma(
    const __half* __restrict__ whh, const float* __restrict__ gbias,
    __half* __restrict__ hout, int layer)
{
    __shared__ uint32_t v_p[32 * VP_STRIDE];
    __shared__ float4 je[64];
    __shared__ uint32_t adj_sm[512];

    int tid = threadIdx.x, w = tid >> 5, lane = tid & 31;
    int g4 = lane >> 2, q4 = lane & 3;
    int it = blockIdx.x, hh = blockIdx.y, b = blockIdx.z;
    int i0 = it * 256, bh = b * HEADS + hh;
    int r0 = w * 32;

    float F1[4], F2[4], adreg[4];
    {
        float mx = fdec(g_asmaxu[layer * (BATCH * HEADS) + bh]);
#pragma unroll
        for (int t = 0; t < 4; t++) {
            float ad = g_ad[bh * NNODE + i0 + r0 + t * 8 + g4];
            adreg[t] = ad;
            float mm = mx + ad;
            float mr = fmaxf(mm, 0.2f * mm);
            F1[t] = __expf(ad - mr);
            F2[t] = __expf(0.2f * ad - mr);
        }
    }
    {
        int jp = tid >> 3, cc = 64 + (tid & 7);
        v_p[jp * VP_STRIDE + cc] = (cc == 64) ? 0x3C003C00u : 0u;
    }

    float acc[2][9][4];
#pragma unroll
    for (int mt = 0; mt < 2; mt++)
#pragma unroll
        for (int n = 0; n < 9; n++)
#pragma unroll
            for (int k = 0; k < 4; k++) acc[mt][n][k] = 0.f;

    const __half* whb = whh + ((size_t)(b * NNODE)) * DIM + hh * 64;
    const uint32_t* adjb = g_adjT + (size_t)b * 32 * NNODE + i0;

    for (int ch = 0; ch < 16; ch++) {
        int j0c = ch * 64;
        __syncthreads();
        {
            int jp = tid >> 3, cb = (tid & 7) * 8;
            const uint4* rA = (const uint4*)(whb + (size_t)(j0c + 2 * jp) * DIM + cb);
            const uint4* rB = (const uint4*)(whb + (size_t)(j0c + 2 * jp + 1) * DIM + cb);
            uint4 a = rA[0], bb4 = rB[0];
            uint4 o0, o1;
            o0.x = prmtb(a.x, bb4.x, 0x5410); o0.y = prmtb(a.x, bb4.x, 0x7632);
            o0.z = prmtb(a.y, bb4.y, 0x5410); o0.w = prmtb(a.y, bb4.y, 0x7632);
            o1.x = prmtb(a.z, bb4.z, 0x5410); o1.y = prmtb(a.z, bb4.z, 0x7632);
            o1.z = prmtb(a.w, bb4.w, 0x5410); o1.w = prmtb(a.w, bb4.w, 0x7632);
            *(uint4*)&v_p[jp * VP_STRIDE + cb] = o0;
            *(uint4*)&v_p[jp * VP_STRIDE + cb + 4] = o1;
        }
        if (tid < 64) {
            float a = g_as[bh * NNODE + j0c + tid];
            je[tid] = make_float4(a, __expf(a), __expf(0.2f * a), 0.f);
        }
        adj_sm[tid] = adjb[(size_t)(2 * ch) * NNODE + tid];
        adj_sm[256 + tid] = adjb[(size_t)(2 * ch + 1) * NNODE + tid];
        __syncthreads();
        uint32_t Aw[2][4];
#pragma unroll
        for (int t = 0; t < 4; t++) {
            Aw[0][t] = adj_sm[r0 + t * 8 + g4];
            Aw[1][t] = adj_sm[256 + r0 + t * 8 + g4];
        }
        uint32_t andall = Aw[0][0] & Aw[0][1] & Aw[0][2] & Aw[0][3]
                        & Aw[1][0] & Aw[1][1] & Aw[1][2] & Aw[1][3];
        bool allones = __all_sync(0xffffffffu, andall == 0xffffffffu);

#pragma unroll
        for (int kb = 0; kb < 4; kb++) {
            int jlo = kb * 16 + 2 * q4;
            float4 jeA = je[jlo];
            float4 jeB = je[jlo + 1];
            float4 jeC = je[jlo + 8];
            float4 jeD = je[jlo + 9];
            uint32_t afr[2][4];
            if (allones) {
#pragma unroll
                for (int t = 0; t < 4; t++) {
                    float pa = slctf(jeA.y * F1[t], jeA.z * F2[t], jeA.x + adreg[t]);
                    float pb = slctf(jeB.y * F1[t], jeB.z * F2[t], jeB.x + adreg[t]);
                    float pc = slctf(jeC.y * F1[t], jeC.z * F2[t], jeC.x + adreg[t]);
                    float pd = slctf(jeD.y * F1[t], jeD.z * F2[t], jeD.x + adreg[t]);
                    afr[t >> 1][t & 1] = pack2(pa, pb);
                    afr[t >> 1][2 + (t & 1)] = pack2(pc, pd);
                }
            } else {
                int half = kb >> 1;
                int s = jlo & 31;
#pragma unroll
                for (int t = 0; t < 4; t++) {
                    uint32_t wv = Aw[half][t];
                    uint32_t b2lo = (wv >> s) & 3u;
                    uint32_t b2hi = (wv >> (s + 8)) & 3u;
                    uint32_t mlo = ((b2lo & 1u) ? 0x0000FFFFu : 0u) |
                                   ((b2lo & 2u) ? 0xFFFF0000u : 0u);
                    uint32_t mhi = ((b2hi & 1u) ? 0x0000FFFFu : 0u) |
                                   ((b2hi & 2u) ? 0xFFFF0000u : 0u);
                    float pa = slctf(jeA.y * F1[t], jeA.z * F2[t], jeA.x + adreg[t]);
                    float pb = slctf(jeB.y * F1[t], jeB.z * F2[t], jeB.x + adreg[t]);
                    float pc = slctf(jeC.y * F1[t], jeC.z * F2[t], jeC.x + adreg[t]);
                    float pd = slctf(jeD.y * F1[t], jeD.z * F2[t], jeD.x + adreg[t]);
                    afr[t >> 1][t & 1] = pack2(pa, pb) & mlo;
                    afr[t >> 1][2 + (t & 1)] = pack2(pc, pd) & mhi;
                }
            }
            const uint32_t* bp = v_p + (kb * 8 + q4) * VP_STRIDE + g4;
#pragma unroll
            for (int nt = 0; nt < 9; nt++) {
                uint32_t b0 = bp[nt * 8];
                uint32_t b1 = bp[nt * 8 + 4 * VP_STRIDE];
                mma_f16(acc[0][nt], afr[0][0], afr[0][1], afr[0][2], afr[0][3], b0, b1);
                mma_f16(acc[1][nt], afr[1][0], afr[1][1], afr[1][2], afr[1][3], b0, b1);
            }
        }
    }
    const float* bp = gbias + hh * 64;
#pragma unroll
    for (int mt = 0; mt < 2; mt++) {
        float z0 = __shfl_sync(0xffffffffu, acc[mt][8][0], lane & 28);
        float z1 = __shfl_sync(0xffffffffu, acc[mt][8][2], lane & 28);
        float iz0 = 1.f / z0;
        float iz1 = 1.f / z1;
        int rowg = i0 + r0 + mt * 16 + g4;
        __half* o0 = hout + ((size_t)(b * NNODE) + rowg) * DIM + hh * 64;
        __half* o1 = o0 + 8 * DIM;
#pragma unroll
        for (int nt = 0; nt < 8; nt++) {
            int cc = nt * 8 + q4 * 2;
            float bx = bp[cc], by = bp[cc + 1];
            float u0x = fmaxf(fmaf(acc[mt][nt][0], iz0, bx), 0.f);
            float u0y = fmaxf(fmaf(acc[mt][nt][1], iz0, by), 0.f);
            float u1x = fmaxf(fmaf(acc[mt][nt][2], iz1, bx), 0.f);
            float u1y = fmaxf(fmaf(acc[mt][nt][3], iz1, by), 0.f);
            *(uint32_t*)(o0 + cc) = pack2(u0x, u0y);
            *(uint32_t*)(o1 + cc) = pack2(u1x, u1y);
        }
    }
}

// ---------------- launch ----------------
extern "C" void kernel_launch(void* const* d_in, const int* in_sizes, int n_in,
                              void* d_out, int out_size)
{
    const float* ego      = (const float*)d_in[0];
    const float* nbr      = (const float*)d_in[1];
    const float* node_w   = (const float*)d_in[2];
    const float* node_b   = (const float*)d_in[3];
    const float* node_g   = (const float*)d_in[4];
    const float* node_bb  = (const float*)d_in[5];
    const float* ego_w    = (const float*)d_in[6];
    const float* ego_b    = (const float*)d_in[7];
    const float* ego_g    = (const float*)d_in[8];
    const float* ego_bb   = (const float*)d_in[9];
    const float* gat_w    = (const float*)d_in[10];
    const float* gat_asrc = (const float*)d_in[11];
    const float* gat_adst = (const float*)d_in[12];
    const float* gat_b    = (const float*)d_in[13];
    const float* proj_w   = (const float*)d_in[14];
    const float* proj_b   = (const float*)d_in[15];
    float* out = (float*)d_out;

    __half *h0h, *h1h, *whh;
    uint32_t* wpack;
    cudaGetSymbolAddress((void**)&h0h, g_h0h);
    cudaGetSymbolAddress((void**)&h1h, g_h1h);
    cudaGetSymbolAddress((void**)&whh, g_whh);
    cudaGetSymbolAddress((void**)&wpack, g_wpack);

    long long hsz = (long long)BATCH * NNODE * DIM;

    embed_kernel<<<BATCH * NNODE / 8, 256>>>(ego, nbr, node_w, node_b, node_g, node_bb,
                                             ego_w, ego_b, ego_g, ego_bb);
    adj_kernel<<<dim3(NNODE / 32, 32, BATCH), 256>>>();
    wprep_kernel<<<448, 256>>>(gat_w, proj_w, out, hsz, (long long)out_size);

    dim3 ggrid(BATCH * NNODE / 128, 2);
    __half* hbuf[2] = { h0h, h1h };
    for (int l = 0; l < 2; l++) {
        tgemm256<false, true><<<ggrid, 256>>>(
            (const uint32_t*)hbuf[l], wpack + (size_t)l * 32768,
            nullptr, nullptr, whh,
            gat_asrc + l * HEADS * 64, gat_adst + l * HEADS * 64, l);
        gat_attn_mma<<<dim3(4, HEADS, BATCH), 256>>>(whh, gat_b + l * DIM,
                                                     hbuf[1 - l], l);
    }
    tgemm256<true, false><<<ggrid, 256>>>(
        (const uint32_t*)h0h, wpack + 2 * 32768,
        proj_b, out, nullptr, nullptr, nullptr, 0);
}

// round 17
// speedup vs baseline: 1.0045x; 1.0014x over previous
#include <cuda_runtime.h>
#include <cuda_fp16.h>
#include <cstdint>

#define BATCH 16
#define NNODE 1024
#define DIM 256
#define HEADS 4
#define NBR 1023
#define TSTEPS 20

// ---------------- scratch (device globals; no allocation allowed) ----------------
__device__ __half g_h0h[BATCH * NNODE * DIM];
__device__ __half g_h1h[BATCH * NNODE * DIM];
__device__ __half g_whh[BATCH * NNODE * DIM];
__device__ uint32_t g_wpack[3 * 128 * 256];
__device__ float g_pos[BATCH * NNODE * 2];
__device__ float g_as[BATCH * HEADS * NNODE];
__device__ float g_ad[BATCH * HEADS * NNODE];
__device__ uint32_t g_asmaxu[2 * BATCH * HEADS];
__device__ uint32_t g_adjT[BATCH * 32 * NNODE];

// ======================= helpers =======================
__device__ __forceinline__ void mma_f16(float* c, uint32_t a0, uint32_t a1,
                                        uint32_t a2, uint32_t a3,
                                        uint32_t b0, uint32_t b1) {
    asm volatile(
        "mma.sync.aligned.m16n8k16.row.col.f32.f16.f16.f32 "
        "{%0,%1,%2,%3}, {%4,%5,%6,%7}, {%8,%9}, {%0,%1,%2,%3};"
        : "+f"(c[0]), "+f"(c[1]), "+f"(c[2]), "+f"(c[3])
        : "r"(a0), "r"(a1), "r"(a2), "r"(a3), "r"(b0), "r"(b1));
}
__device__ __forceinline__ float slctf(float a, float b, float c) {
    float d;
    asm("slct.f32.f32 %0, %1, %2, %3;" : "=f"(d) : "f"(a), "f"(b), "f"(c));
    return d;
}
__device__ __forceinline__ uint32_t pack2(float lo, float hi) {
    uint32_t d;
    asm("cvt.rn.f16x2.f32 %0, %1, %2;" : "=r"(d) : "f"(hi), "f"(lo));
    return d;
}
__device__ __forceinline__ uint32_t prmtb(uint32_t a, uint32_t b, uint32_t s) {
    uint32_t d;
    asm("prmt.b32 %0, %1, %2, %3;" : "=r"(d) : "r"(a), "r"(b), "r"(s));
    return d;
}
__device__ __forceinline__ uint32_t fenc(float f) {
    uint32_t b = __float_as_uint(f);
    return ((int)b < 0) ? ~b : (b | 0x80000000u);
}
__device__ __forceinline__ float fdec(uint32_t u) {
    return __uint_as_float((u & 0x80000000u) ? (u ^ 0x80000000u) : ~u);
}

// ---------------- weight prep (+output-tail zero) ----------------
__global__ __launch_bounds__(256) void wprep_kernel(
    const float* __restrict__ gat_w, const float* __restrict__ proj_w,
    float* __restrict__ out, long long tstart, long long ttotal)
{
    if (blockIdx.x < 384) {
        int wsel = blockIdx.x >> 7;
        int kp = blockIdx.x & 127;
        int n = threadIdx.x;
        const float* W = (wsel < 2) ? gat_w + (size_t)wsel * 65536 : proj_w;
        float lo = W[(size_t)(2 * kp) * 256 + n];
        float hi = W[(size_t)(2 * kp + 1) * 256 + n];
        g_wpack[(size_t)wsel * 32768 + kp * 256 + n] = pack2(lo, hi);
    } else {
        long long i = tstart + (long long)(blockIdx.x - 384) * 256 + threadIdx.x;
        while (i < ttotal) { out[i] = 0.f; i += 64LL * 256; }
    }
}

// ---------------- embed: 8 nodes per block, fp16 output ----------------
__global__ __launch_bounds__(256) void embed_kernel(
    const float* __restrict__ ego, const float* __restrict__ nbr,
    const float* __restrict__ node_w, const float* __restrict__ node_b,
    const float* __restrict__ node_g, const float* __restrict__ node_bb,
    const float* __restrict__ ego_w, const float* __restrict__ ego_b,
    const float* __restrict__ ego_g, const float* __restrict__ ego_bb)
{
    int t = threadIdx.x;
    int bn0 = blockIdx.x * 8;
    __shared__ float f[8][5];
    __shared__ float ws[8][8], wq[8][8];
    if (t < 40) {
        int nn = t / 5, k = t - nn * 5;
        int bn = bn0 + nn;
        int b = bn >> 10, n = bn & 1023;
        float v = (n == 0) ? ego[(b * TSTEPS + TSTEPS - 1) * 7 + k]
                           : nbr[((b * NBR + (n - 1)) * TSTEPS + TSTEPS - 1) * 11 + k];
        f[nn][k] = v;
        if (k < 2) g_pos[bn * 2 + k] = v;
    }
    __syncthreads();
    float wn[5];
#pragma unroll
    for (int k = 0; k < 5; k++) wn[k] = node_w[k * DIM + t];
    float nb = node_b[t];
    int lane = t & 31, w = t >> 5;
    float vv[8];
#pragma unroll
    for (int nn = 0; nn < 8; nn++) {
        int n = (bn0 + nn) & 1023;
        float v;
        if (n == 0) {
            v = ego_b[t];
#pragma unroll
            for (int k = 0; k < 5; k++) v = fmaf(f[nn][k], ego_w[k * DIM + t], v);
        } else {
            v = nb;
#pragma unroll
            for (int k = 0; k < 5; k++) v = fmaf(f[nn][k], wn[k], v);
        }
        v = fmaxf(v, 0.f);
        vv[nn] = v;
        float s = v, q = v * v;
#pragma unroll
        for (int o = 16; o; o >>= 1) {
            s += __shfl_down_sync(0xffffffffu, s, o);
            q += __shfl_down_sync(0xffffffffu, q, o);
        }
        if (lane == 0) { ws[nn][w] = s; wq[nn][w] = q; }
    }
    __syncthreads();
    float ng = node_g[t], nbb = node_bb[t];
#pragma unroll
    for (int nn = 0; nn < 8; nn++) {
        int bn = bn0 + nn;
        int n = bn & 1023;
        float sum = 0.f, sq = 0.f;
#pragma unroll
        for (int i = 0; i < 8; i++) { sum += ws[nn][i]; sq += wq[nn][i]; }
        float mean = sum * (1.f / 256.f);
        float var = fmaxf(sq * (1.f / 256.f) - mean * mean, 0.f);
        float inv = rsqrtf(var + 1e-5f);
        float gg = ng, bb2 = nbb;
        if (n == 0) { gg = ego_g[t]; bb2 = ego_bb[t]; }
        g_h0h[(size_t)bn * DIM + t] = __float2half_rn((vv[nn] - mean) * inv * gg + bb2);
    }
}

// ---------------- adjacency bitmask + asmax buffer init ----------------
__global__ __launch_bounds__(256) void adj_kernel()
{
    int b = blockIdx.z, jw = blockIdx.y;
    int lane = threadIdx.x & 31, w = threadIdx.x >> 5;
    if (blockIdx.x == 0 && jw == 0 && threadIdx.x < 8) {
        int l = threadIdx.x >> 2, h = threadIdx.x & 3;
        g_asmaxu[l * (BATCH * HEADS) + b * HEADS + h] = 0u;
    }
    int j = jw * 32 + lane;
    float2 pj = ((const float2*)g_pos)[b * NNODE + j];
    int i0 = blockIdx.x * 32 + w;
#pragma unroll
    for (int q = 0; q < 4; q++) {
        int i = i0 + q * 8;
        float2 pi = ((const float2*)g_pos)[b * NNODE + i];
        float dx = pj.x - pi.x, dy = pj.y - pi.y;
        bool a = (fmaf(dx, dx, dy * dy) < 2500.f) || (i == j);
        uint32_t word = __ballot_sync(0xffffffffu, a);
        if (lane == 0) g_adjT[(b * 32 + jw) * NNODE + i] = word;
    }
}

// ---------------- fp16 GEMM 128x128 tile, warp covers one head (SAD in-warp) ----
#define GA_STRIDE 20
#define GBW_STRIDE 136
template <bool BIAS, bool SAD>
__global__ __launch_bounds__(256, 2) void tgemm256(
    const uint32_t* __restrict__ A_pack, const uint32_t* __restrict__ W_pack,
    const float* __restrict__ bias, float* __restrict__ Cf, __half* __restrict__ Ch,
    const float* __restrict__ asrc, const float* __restrict__ adst,
    int sadLayer)
{
    __shared__ uint32_t As_p[128 * GA_STRIDE];
    __shared__ uint32_t Bs_p[16 * GBW_STRIDE];
    int tid = threadIdx.x, w = tid >> 5, lane = tid & 31;
    int g4 = lane >> 2, q4 = lane & 3;
    int m0 = blockIdx.x * 128, n0 = blockIdx.y * 128;
    int wm = w & 3, wn = w >> 2;
    int r0 = wm * 32, c0 = wn * 64;

    int arow = tid >> 2, af4 = tid & 3;
    int brow = tid >> 4, bf4 = tid & 15;
    const uint4* Ag = (const uint4*)(A_pack + (size_t)(m0 + arow) * 128 + af4 * 4);
    const uint32_t* WgBase = W_pack + (size_t)brow * 256 + n0 + bf4 * 4;

    float acc[2][8][4];
#pragma unroll
    for (int mt = 0; mt < 2; mt++)
#pragma unroll
        for (int nt = 0; nt < 8; nt++)
#pragma unroll
            for (int k = 0; k < 4; k++) acc[mt][nt][k] = 0.f;

    uint4 pa0 = Ag[0];
    uint4 pa1 = Ag[(size_t)64 * 32];
    uint4 pb0 = *(const uint4*)WgBase;
    uint4 pb1 = *(const uint4*)(WgBase + 64);

    for (int kc = 0; kc < 8; kc++) {
        __syncthreads();
        *(uint4*)&As_p[arow * GA_STRIDE + af4 * 4] = pa0;
        *(uint4*)&As_p[(arow + 64) * GA_STRIDE + af4 * 4] = pa1;
        *(uint4*)&Bs_p[brow * GBW_STRIDE + bf4 * 4] = pb0;
        *(uint4*)&Bs_p[brow * GBW_STRIDE + 64 + bf4 * 4] = pb1;
        __syncthreads();
        if (kc < 7) {
            const uint4* Agn = (const uint4*)((const uint32_t*)Ag + (kc + 1) * 16);
            const uint32_t* Wgn = WgBase + (size_t)(kc + 1) * 16 * 256;
            pa0 = Agn[0];
            pa1 = Agn[(size_t)64 * 32];
            pb0 = *(const uint4*)Wgn;
            pb1 = *(const uint4*)(Wgn + 64);
        }
#pragma unroll
        for (int kbb = 0; kbb < 2; kbb++) {
            const uint32_t* ap = As_p + (r0 + g4) * GA_STRIDE + kbb * 8 + q4;
            uint32_t a00 = ap[0];
            uint32_t a01 = ap[8 * GA_STRIDE];
            uint32_t a02 = ap[4];
            uint32_t a03 = ap[8 * GA_STRIDE + 4];
            uint32_t a10 = ap[16 * GA_STRIDE];
            uint32_t a11 = ap[24 * GA_STRIDE];
            uint32_t a12 = ap[16 * GA_STRIDE + 4];
            uint32_t a13 = ap[24 * GA_STRIDE + 4];
            const uint32_t* bp = Bs_p + (kbb * 8 + q4) * GBW_STRIDE + c0 + g4;
#pragma unroll
            for (int nt = 0; nt < 8; nt++) {
                uint32_t b0 = bp[nt * 8];
                uint32_t b1 = bp[nt * 8 + 4 * GBW_STRIDE];
                mma_f16(acc[0][nt], a00, a01, a02, a03, b0, b1);
                mma_f16(acc[1][nt], a10, a11, a12, a13, b0, b1);
            }
        }
    }
    // ---- C store ----
#pragma unroll
    for (int mt = 0; mt < 2; mt++) {
        int row = m0 + r0 + mt * 16 + g4;
#pragma unroll
        for (int nt = 0; nt < 8; nt++) {
            int cc = nt * 8 + q4 * 2;
            if (BIAS) {
                float bx = bias[n0 + c0 + cc], by = bias[n0 + c0 + cc + 1];
                float2 u0, u1;
                u0.x = acc[mt][nt][0] + bx; u0.y = acc[mt][nt][1] + by;
                u1.x = acc[mt][nt][2] + bx; u1.y = acc[mt][nt][3] + by;
                *(float2*)&Cf[(size_t)row * 256 + n0 + c0 + cc] = u0;
                *(float2*)&Cf[(size_t)(row + 8) * 256 + n0 + c0 + cc] = u1;
            } else {
                *(uint32_t*)&Ch[(size_t)row * 256 + n0 + c0 + cc] =
                    pack2(acc[mt][nt][0], acc[mt][nt][1]);
                *(uint32_t*)&Ch[(size_t)(row + 8) * 256 + n0 + c0 + cc] =
                    pack2(acc[mt][nt][2], acc[mt][nt][3]);
            }
        }
    }
    // ---- fused a_src / a_dst + asmax: each warp owns head hh, rows r0..r0+31 ----
    if (SAD) {
        int hh = blockIdx.y * 2 + wn;
        int b = m0 >> 10;
        int bh = b * HEADS + hh;
        float as_c[16], ad_c[16];
#pragma unroll
        for (int nt = 0; nt < 8; nt++) {
            int cc = nt * 8 + q4 * 2;
            as_c[nt * 2] = asrc[hh * 64 + cc];
            as_c[nt * 2 + 1] = asrc[hh * 64 + cc + 1];
            ad_c[nt * 2] = adst[hh * 64 + cc];
            ad_c[nt * 2 + 1] = adst[hh * 64 + cc + 1];
        }
        float mloc = -1e30f;
#pragma unroll
        for (int mt = 0; mt < 2; mt++) {
            float sAs = 0.f, sAd = 0.f, sBs = 0.f, sBd = 0.f;
#pragma unroll
            for (int nt = 0; nt < 8; nt++) {
                sAs += acc[mt][nt][0] * as_c[nt * 2] + acc[mt][nt][1] * as_c[nt * 2 + 1];
                sBs += acc[mt][nt][2] * as_c[nt * 2] + acc[mt][nt][3] * as_c[nt * 2 + 1];
                sAd += acc[mt][nt][0] * ad_c[nt * 2] + acc[mt][nt][1] * ad_c[nt * 2 + 1];
                sBd += acc[mt][nt][2] * ad_c[nt * 2] + acc[mt][nt][3] * ad_c[nt * 2 + 1];
            }
#pragma unroll
            for (int o = 1; o < 4; o <<= 1) {
                sAs += __shfl_xor_sync(0xffffffffu, sAs, o);
                sAd += __shfl_xor_sync(0xffffffffu, sAd, o);
                sBs += __shfl_xor_sync(0xffffffffu, sBs, o);
                sBd += __shfl_xor_sync(0xffffffffu, sBd, o);
            }
            int n = (m0 & 1023) + r0 + mt * 16 + g4;
            if (q4 == 0) {
                g_as[bh * NNODE + n] = sAs;
                g_ad[bh * NNODE + n] = sAd;
                g_as[bh * NNODE + n + 8] = sBs;
                g_ad[bh * NNODE + n + 8] = sBd;
            }
            mloc = fmaxf(mloc, fmaxf(sAs, sBs));
        }
#pragma unroll
        for (int o = 16; o; o >>= 1)
            mloc = fmaxf(mloc, __shfl_xor_sync(0xffffffffu, mloc, o));
        if (lane == 0)
            atomicMax(&g_asmaxu[sadLayer * (BATCH * HEADS) + bh], fenc(mloc));
    }
}

// ---------------- GAT attention: fp16 m16n8k16 MMA, fp16 wh input ----
#define VP_STRIDE 72
__global__ __launch_bounds__(256, 2) void gat_attn_mma(
    const __half* __restrict__ whh, const float* __restrict__ gbias,
    __half* __restrict__ hout, int layer)
{
    __shared__ uint32_t v_p[32 * VP_STRIDE];
    __shared__ float4 je[64];
    __shared__ uint32_t adj_sm[512];

    int tid = threadIdx.x, w = tid >> 5, lane = tid & 31;
    int g4 = lane >> 2, q4 = lane & 3;
    int it = blockIdx.x, hh = blockIdx.y, b = blockIdx.z;
    int i0 = it * 256, bh = b * HEADS + hh;
    int r0 = w * 32;

    float F1[4], F2[4], adreg[4];
    {
        float mx = fdec(g_asmaxu[layer * (BATCH * HEADS) + bh]);
#pragma unroll
        for (int t = 0; t < 4; t++) {
            float ad = g_ad[bh * NNODE + i0 + r0 + t * 8 + g4];
            adreg[t] = ad;
            float mm = mx + ad;
            float mr = fmaxf(mm, 0.2f * mm);
            F1[t] = __expf(ad - mr);
            F2[t] = __expf(0.2f * ad - mr);
        }
    }
    {
        int jp = tid >> 3, cc = 64 + (tid & 7);
        v_p[jp * VP_STRIDE + cc] = (cc == 64) ? 0x3C003C00u : 0u;
    }

    float acc[2][9][4];
#pragma unroll
    for (int mt = 0; mt < 2; mt++)
#pragma unroll
        for (int n = 0; n < 9; n++)
#pragma unroll
            for (int k = 0; k < 4; k++) acc[mt][n][k] = 0.f;

    const __half* whb = whh + ((size_t)(b * NNODE)) * DIM + hh * 64;
    const uint32_t* adjb = g_adjT + (size_t)b * 32 * NNODE + i0;

    for (int ch = 0; ch < 16; ch++) {
        int j0c = ch * 64;
        __syncthreads();
        {
            int jp = tid >> 3, cb = (tid & 7) * 8;
            const uint4* rA = (const uint4*)(whb + (size_t)(j0c + 2 * jp) * DIM + cb);
            const uint4* rB = (const uint4*)(whb + (size_t)(j0c + 2 * jp + 1) * DIM + cb);
            uint4 a = rA[0], bb4 = rB[0];
            uint4 o0, o1;
            o0.x = prmtb(a.x, bb4.x, 0x5410); o0.y = prmtb(a.x, bb4.x, 0x7632);
            o0.z = prmtb(a.y, bb4.y, 0x5410); o0.w = prmtb(a.y, bb4.y, 0x7632);
            o1.x = prmtb(a.z, bb4.z, 0x5410); o1.y = prmtb(a.z, bb4.z, 0x7632);
            o1.z = prmtb(a.w, bb4.w, 0x5410); o1.w = prmtb(a.w, bb4.w, 0x7632);
            *(uint4*)&v_p[jp * VP_STRIDE + cb] = o0;
            *(uint4*)&v_p[jp * VP_STRIDE + cb + 4] = o1;
        }
        if (tid < 64) {
            float a = g_as[bh * NNODE + j0c + tid];
            je[tid] = make_float4(a, __expf(a), __expf(0.2f * a), 0.f);
        }
        adj_sm[tid] = adjb[(size_t)(2 * ch) * NNODE + tid];
        adj_sm[256 + tid] = adjb[(size_t)(2 * ch + 1) * NNODE + tid];
        __syncthreads();
        uint32_t Aw[2][4];
#pragma unroll
        for (int t = 0; t < 4; t++) {
            Aw[0][t] = adj_sm[r0 + t * 8 + g4];
            Aw[1][t] = adj_sm[256 + r0 + t * 8 + g4];
        }
        uint32_t andall = Aw[0][0] & Aw[0][1] & Aw[0][2] & Aw[0][3]
                        & Aw[1][0] & Aw[1][1] & Aw[1][2] & Aw[1][3];
        bool allones = __all_sync(0xffffffffu, andall == 0xffffffffu);

#pragma unroll
        for (int kb = 0; kb < 4; kb++) {
            int jlo = kb * 16 + 2 * q4;
            float4 jeA = je[jlo];
            float4 jeB = je[jlo + 1];
            float4 jeC = je[jlo + 8];
            float4 jeD = je[jlo + 9];
            uint32_t afr[2][4];
            if (allones) {
#pragma unroll
                for (int t = 0; t < 4; t++) {
                    float pa = slctf(jeA.y * F1[t], jeA.z * F2[t], jeA.x + adreg[t]);
                    float pb = slctf(jeB.y * F1[t], jeB.z * F2[t], jeB.x + adreg[t]);
                    float pc = slctf(jeC.y * F1[t], jeC.z * F2[t], jeC.x + adreg[t]);
                    float pd = slctf(jeD.y * F1[t], jeD.z * F2[t], jeD.x + adreg[t]);
                    afr[t >> 1][t & 1] = pack2(pa, pb);
                    afr[t >> 1][2 + (t & 1)] = pack2(pc, pd);
                }
            } else {
                int half = kb >> 1;
                int s = jlo & 31;
#pragma unroll
                for (int t = 0; t < 4; t++) {
                    uint32_t wv = Aw[half][t];
                    uint32_t b2lo = (wv >> s) & 3u;
                    uint32_t b2hi = (wv >> (s + 8)) & 3u;
                    uint32_t mlo = ((b2lo & 1u) ? 0x0000FFFFu : 0u) |
                                   ((b2lo & 2u) ? 0xFFFF0000u : 0u);
                    uint32_t mhi = ((b2hi & 1u) ? 0x0000FFFFu : 0u) |
                                   ((b2hi & 2u) ? 0xFFFF0000u : 0u);
                    float pa = slctf(jeA.y * F1[t], jeA.z * F2[t], jeA.x + adreg[t]);
                    float pb = slctf(jeB.y * F1[t], jeB.z * F2[t], jeB.x + adreg[t]);
                    float pc = slctf(jeC.y * F1[t], jeC.z * F2[t], jeC.x + adreg[t]);
                    float pd = slctf(jeD.y * F1[t], jeD.z * F2[t], jeD.x + adreg[t]);
                    afr[t >> 1][t & 1] = pack2(pa, pb) & mlo;
                    afr[t >> 1][2 + (t & 1)] = pack2(pc, pd) & mhi;
                }
            }
            const uint32_t* bp = v_p + (kb * 8 + q4) * VP_STRIDE + g4;
#pragma unroll
            for (int nt = 0; nt < 9; nt++) {
                uint32_t b0 = bp[nt * 8];
                uint32_t b1 = bp[nt * 8 + 4 * VP_STRIDE];
                mma_f16(acc[0][nt], afr[0][0], afr[0][1], afr[0][2], afr[0][3], b0, b1);
                mma_f16(acc[1][nt], afr[1][0], afr[1][1], afr[1][2], afr[1][3], b0, b1);
            }
        }
    }
    const float* bp = gbias + hh * 64;
#pragma unroll
    for (int mt = 0; mt < 2; mt++) {
        float z0 = __shfl_sync(0xffffffffu, acc[mt][8][0], lane & 28);
        float z1 = __shfl_sync(0xffffffffu, acc[mt][8][2], lane & 28);
        float iz0 = 1.f / z0;
        float iz1 = 1.f / z1;
        int rowg = i0 + r0 + mt * 16 + g4;
        __half* o0 = hout + ((size_t)(b * NNODE) + rowg) * DIM + hh * 64;
        __half* o1 = o0 + 8 * DIM;
#pragma unroll
        for (int nt = 0; nt < 8; nt++) {
            int cc = nt * 8 + q4 * 2;
            float bx = bp[cc], by = bp[cc + 1];
            float u0x = fmaxf(fmaf(acc[mt][nt][0], iz0, bx), 0.f);
            float u0y = fmaxf(fmaf(acc[mt][nt][1], iz0, by), 0.f);
            float u1x = fmaxf(fmaf(acc[mt][nt][2], iz1, bx), 0.f);
            float u1y = fmaxf(fmaf(acc[mt][nt][3], iz1, by), 0.f);
            *(uint32_t*)(o0 + cc) = pack2(u0x, u0y);
            *(uint32_t*)(o1 + cc) = pack2(u1x, u1y);
        }
    }
}

// ---------------- launch ----------------
extern "C" void kernel_launch(void* const* d_in, const int* in_sizes, int n_in,
                              void* d_out, int out_size)
{
    const float* ego      = (const float*)d_in[0];
    const float* nbr      = (const float*)d_in[1];
    const float* node_w   = (const float*)d_in[2];
    const float* node_b   = (const float*)d_in[3];
    const float* node_g   = (const float*)d_in[4];
    const float* node_bb  = (const float*)d_in[5];
    const float* ego_w    = (const float*)d_in[6];
    const float* ego_b    = (const float*)d_in[7];
    const float* ego_g    = (const float*)d_in[8];
    const float* ego_bb   = (const float*)d_in[9];
    const float* gat_w    = (const float*)d_in[10];
    const float* gat_asrc = (const float*)d_in[11];
    const float* gat_adst = (const float*)d_in[12];
    const float* gat_b    = (const float*)d_in[13];
    const float* proj_w   = (const float*)d_in[14];
    const float* proj_b   = (const float*)d_in[15];
    float* out = (float*)d_out;

    __half *h0h, *h1h, *whh;
    uint32_t* wpack;
    cudaGetSymbolAddress((void**)&h0h, g_h0h);
    cudaGetSymbolAddress((void**)&h1h, g_h1h);
    cudaGetSymbolAddress((void**)&whh, g_whh);
    cudaGetSymbolAddress((void**)&wpack, g_wpack);

    long long hsz = (long long)BATCH * NNODE * DIM;

    embed_kernel<<<BATCH * NNODE / 8, 256>>>(ego, nbr, node_w, node_b, node_g, node_bb,
                                             ego_w, ego_b, ego_g, ego_bb);
    adj_kernel<<<dim3(NNODE / 32, 32, BATCH), 256>>>();
    wprep_kernel<<<448, 256>>>(gat_w, proj_w, out, hsz, (long long)out_size);

    dim3 ggrid(BATCH * NNODE / 128, 2);
    __half* hbuf[2] = { h0h, h1h };
    for (int l = 0; l < 2; l++) {
        tgemm256<false, true><<<ggrid, 256>>>(
            (const uint32_t*)hbuf[l], wpack + (size_t)l * 32768,
            nullptr, nullptr, whh,
            gat_asrc + l * HEADS * 64, gat_adst + l * HEADS * 64, l);
        gat_attn_mma<<<dim3(4, HEADS, BATCH), 256>>>(whh, gat_b + l * DIM,
                                                     hbuf[1 - l], l);
    }
    tgemm256<true, false><<<ggrid, 256>>>(
        (const uint32_t*)h0h, wpack + 2 * 32768,
        proj_b, out, nullptr, nullptr, nullptr, 0);
}